// round 15
// baseline (speedup 1.0000x reference)
#include <cuda_runtime.h>
#include <cuda_fp16.h>

#define T_SEQ 2048
#define BATCH 4
#define DIN   512
#define DOUT  256
#define NROWS 16384   // 2*BATCH*T_SEQ (q rows then k rows)
#define NTILES 2048   // 4 batch x 16 (t/128) x 32 (s/64)
#define ATTN_GRID 152

// Scratch (static __device__ — no allocation)
__device__ unsigned short g_X16[NROWS * DIN];
__device__ unsigned short g_h1[NROWS * DOUT];
__device__ unsigned short g_h2[NROWS * DOUT];
__device__ unsigned short g_A[NROWS * DOUT];
__device__ unsigned short g_B[NROWS * DOUT];
__device__ unsigned short g_Wt1a[DOUT * DIN];
__device__ unsigned short g_Wt1b[DOUT * DIN];
__device__ unsigned short g_Wt2a[DOUT * DOUT];
__device__ unsigned short g_Wt2b[DOUT * DOUT];

// ---------------------------------------------------------------------------
// helpers
// ---------------------------------------------------------------------------
__device__ __forceinline__ float f_ex2(float x) {
    float y; asm("ex2.approx.ftz.f32 %0, %1;" : "=f"(y) : "f"(x)); return y;
}
__device__ __forceinline__ float f_lg2(float x) {
    float y; asm("lg2.approx.ftz.f32 %0, %1;" : "=f"(y) : "f"(x)); return y;
}
__device__ __forceinline__ float f_rcp(float x) {
    float y; asm("rcp.approx.ftz.f32 %0, %1;" : "=f"(y) : "f"(x)); return y;
}
__device__ __forceinline__ void mma_f16(
    float& c0, float& c1, float& c2, float& c3,
    unsigned a0, unsigned a1, unsigned a2, unsigned a3,
    unsigned b0, unsigned b1)
{
    asm("mma.sync.aligned.m16n8k16.row.col.f32.f16.f16.f32 "
        "{%0,%1,%2,%3}, {%4,%5,%6,%7}, {%8,%9}, {%0,%1,%2,%3};"
        : "+f"(c0), "+f"(c1), "+f"(c2), "+f"(c3)
        : "r"(a0), "r"(a1), "r"(a2), "r"(a3), "r"(b0), "r"(b1));
}
__device__ __forceinline__ void ldsm_x4(unsigned& r0, unsigned& r1,
                                        unsigned& r2, unsigned& r3, unsigned a) {
    asm volatile("ldmatrix.sync.aligned.m8n8.x4.shared.b16 {%0,%1,%2,%3}, [%4];"
                 : "=r"(r0), "=r"(r1), "=r"(r2), "=r"(r3) : "r"(a));
}
__device__ __forceinline__ void cp16(void* d, const void* s) {
    unsigned a = (unsigned)__cvta_generic_to_shared(d);
    asm volatile("cp.async.cg.shared.global [%0], [%1], 16;" :: "r"(a), "l"(s));
}
__device__ __forceinline__ void cp_commit() {
    asm volatile("cp.async.commit_group;");
}
template<int N> __device__ __forceinline__ void cp_wait() {
    asm volatile("cp.async.wait_group %0;" :: "n"(N));
}

#define LN2   0.69314718056f
#define RLN2  1.44269504089f

__device__ __forceinline__ float softplus_fast(float x) {
    float e = f_ex2(-fabsf(x) * RLN2);
    return fmaxf(x, 0.f) + f_lg2(1.f + e) * LN2;
}

// HardKuma epilogue, fused-Stirling Beta
__device__ __forceinline__ float kuma_out(float ar, float br) {
    const float K_T0 = -3.58496250072f;   // log2(1/12)
    const float K_T1 = -0.12553088208f;   // log2(11/12)
    float a  = fminf(fmaxf(softplus_fast(ar), 0.01f), 100.f);
    float bb = fminf(fmaxf(softplus_fast(br), 0.01f), 100.f);
    float u0 = f_ex2(a * K_T0);
    float u1 = f_ex2(a * K_T1);
    float E0 = f_ex2(bb * f_lg2(1.f - u0));  // 1 - p0
    float p1 = f_ex2(bb * f_lg2(1.f - u1));
    float pc = E0 - p1;

    float g  = 1.f + f_rcp(a);
    float s  = g + bb;
    float y1 = g + 4.f, y2 = bb + 4.f, y3 = s + 4.f;
    float L1 = f_lg2(y1), L2 = f_lg2(y2), L3 = f_lg2(y3);
    float pg = g  * (g  + 1.f) * (g  + 2.f) * (g  + 3.f);
    float pb = bb * (bb + 1.f) * (bb + 2.f) * (bb + 3.f);
    float ps = s  * (s  + 1.f) * (s  + 2.f) * (s  + 3.f);
    float pgb = pg * pb;
    float d3  = y1 * y2 * y3;
    float inv = f_rcp(d3 * pgb);
    float n   = fmaf(y1, y3, fmaf(y2, y3, -y1 * y2));
    float c   = 0.08333333333f * (n * pgb) * inv;
    float R   = ps * d3 * inv;
    float lm2 = (y1 - 0.5f) * L1 + (y2 - 0.5f) * L2 - (y3 - 0.5f) * L3
              + (c - 3.08106146679f) * RLN2;
    float mean = bb * R * f_ex2(lm2);
    mean = fminf(fmaxf(fmaf(1.2f, mean, -0.1f), 0.f), 1.f);

    float zo = (1.f - E0 > p1) ? 0.f : 1.f;
    return (pc < 0.5f) ? zo : mean;
}

// ---------------------------------------------------------------------------
// Prep kernel (unchanged)
// ---------------------------------------------------------------------------
#define QK_ELEMS (NROWS * DIN)
#define CVT_BLOCKS (QK_ELEMS / 2048)   // 4096

__global__ void prep_kernel(
    const float* __restrict__ q,  const float* __restrict__ k, __half* __restrict__ X,
    const float* __restrict__ Wa1, const float* __restrict__ Wb1,
    const float* __restrict__ Wa2, const float* __restrict__ Wb2,
    __half* __restrict__ T1a, __half* __restrict__ T1b,
    __half* __restrict__ T2a, __half* __restrict__ T2b)
{
    int tid = threadIdx.x;
    if (blockIdx.x < CVT_BLOCKS) {
        long i = ((long)blockIdx.x * 256 + tid) * 8;
        const long half_pt = (long)(NROWS / 2) * DIN;
        const float* src = (i < half_pt) ? q + i : k + (i - half_pt);
        float4 v0 = *(const float4*)(src);
        float4 v1 = *(const float4*)(src + 4);
        __half2 h[4];
        h[0] = __floats2half2_rn(v0.x, v0.y);
        h[1] = __floats2half2_rn(v0.z, v0.w);
        h[2] = __floats2half2_rn(v1.x, v1.y);
        h[3] = __floats2half2_rn(v1.z, v1.w);
        *(uint4*)(X + i) = *(uint4*)h;
        return;
    }
    __shared__ float t[32][33];
    int idx = blockIdx.x - CVT_BLOCKS;
    int z  = idx >> 7;
    int rem = idx & 127;
    int gy = rem >> 4, gx = rem & 15;
    int K = (z < 2) ? DIN : DOUT;
    if (gx * 32 >= K) return;
    const float* S = (z == 0) ? Wa1 : (z == 1) ? Wb1 : (z == 2) ? Wa2 : Wb2;
    __half*      D = (z == 0) ? T1a : (z == 1) ? T1b : (z == 2) ? T2a : T2b;

    int kb = gx * 32, nb = gy * 32;
    int x = tid & 31, y = tid >> 5;
#pragma unroll
    for (int i = 0; i < 32; i += 8)
        t[y + i][x] = S[(long)(kb + y + i) * DOUT + nb + x];
    __syncthreads();
#pragma unroll
    for (int i = 0; i < 32; i += 8)
        D[(long)(nb + y + i) * K + kb + x] = __float2half(t[x][y + i]);
}

// ---------------------------------------------------------------------------
// fp16 MLP GEMM (unchanged from R13)
// ---------------------------------------------------------------------------
#define MLPH_TILE_U32 2560
#define MLPH_SMEM_BYTES (4 * 2 * MLPH_TILE_U32 * 4)

__global__ void __launch_bounds__(256, 2) mlp_f16_kernel(
    const __half* __restrict__ X1, const __half* __restrict__ Wt1,
    const float* __restrict__ bias1, __half* __restrict__ C1,
    const __half* __restrict__ X2, const __half* __restrict__ Wt2,
    const float* __restrict__ bias2, __half* __restrict__ C2,
    int K)
{
    extern __shared__ unsigned sm[];
    unsigned* ASb = sm;
    unsigned* BSb = sm + 4 * MLPH_TILE_U32;

    int set = blockIdx.x >> 1;
    int bn  = blockIdx.x & 1;
    long rbase = (long)blockIdx.y * 128;

    const __half* X    = (set ? X2 : X1) + rbase * K;
    const __half* Wb   = (set ? Wt2 : Wt1) + (long)(bn * 128) * K;
    const float*  bias = set ? bias2 : bias1;
    __half*       C    = set ? C2  : C1;

    int tid = threadIdx.x;
    int wid = tid >> 5, lane = tid & 31;
    int wm  = wid >> 2, wn = wid & 3;
    int g   = lane >> 2, t4 = lane & 3;

    int r0 = tid >> 2,          c0 = tid & 3;
    int r1 = (tid + 256) >> 2,  c1 = (tid + 256) & 3;

    int l7 = lane & 7, l8 = (lane >> 3) & 1, l16 = (lane >> 4) & 1;
    unsigned aoff = (unsigned)((wm * 64 + l7 + l8 * 8) * 80 + l16 * 16);
    unsigned boff = (unsigned)((wn * 32 + l7 + l16 * 8) * 80 + l8 * 16);
    unsigned aBase = (unsigned)__cvta_generic_to_shared(ASb);
    unsigned bBase = (unsigned)__cvta_generic_to_shared(BSb);

    float acc[4][4][4];
#pragma unroll
    for (int mt = 0; mt < 4; mt++)
#pragma unroll
        for (int nt = 0; nt < 4; nt++)
#pragma unroll
            for (int c = 0; c < 4; c++) acc[mt][nt][c] = 0.f;

    const int ITERS = K >> 5;

#define MLP_ISSUE(ki) do {                                                    \
        int st_ = (ki) & 3; int k0_ = (ki) << 5;                              \
        unsigned* A_ = ASb + st_ * MLPH_TILE_U32;                             \
        unsigned* B_ = BSb + st_ * MLPH_TILE_U32;                             \
        cp16(A_ + r0 * 20 + c0 * 4, X  + (long)r0 * K + k0_ + c0 * 8);        \
        cp16(A_ + r1 * 20 + c1 * 4, X  + (long)r1 * K + k0_ + c1 * 8);        \
        cp16(B_ + r0 * 20 + c0 * 4, Wb + (long)r0 * K + k0_ + c0 * 8);        \
        cp16(B_ + r1 * 20 + c1 * 4, Wb + (long)r1 * K + k0_ + c1 * 8);        \
    } while (0)

    MLP_ISSUE(0); cp_commit();
    MLP_ISSUE(1); cp_commit();
    MLP_ISSUE(2); cp_commit();

    for (int it = 0; it < ITERS; it++) {
        cp_wait<2>();
        __syncthreads();
        if (it + 3 < ITERS) MLP_ISSUE(it + 3);
        cp_commit();

        int st = it & 3;
        unsigned aS = aBase + st * (MLPH_TILE_U32 * 4);
        unsigned bS = bBase + st * (MLPH_TILE_U32 * 4);

#pragma unroll
        for (int k16 = 0; k16 < 2; k16++) {
            unsigned kbyt = k16 * 32;
            unsigned af[4][4], bf[2][4];
#pragma unroll
            for (int mt = 0; mt < 4; mt++)
                ldsm_x4(af[mt][0], af[mt][1], af[mt][2], af[mt][3],
                        aS + aoff + mt * 1280 + kbyt);
#pragma unroll
            for (int ntp = 0; ntp < 2; ntp++)
                ldsm_x4(bf[ntp][0], bf[ntp][1], bf[ntp][2], bf[ntp][3],
                        bS + boff + ntp * 1280 + kbyt);
#pragma unroll
            for (int nt = 0; nt < 4; nt++) {
                unsigned b0 = bf[nt >> 1][(nt & 1) * 2];
                unsigned b1 = bf[nt >> 1][(nt & 1) * 2 + 1];
#pragma unroll
                for (int mt = 0; mt < 4; mt++)
                    mma_f16(acc[mt][nt][0], acc[mt][nt][1],
                            acc[mt][nt][2], acc[mt][nt][3],
                            af[mt][0], af[mt][1], af[mt][2], af[mt][3],
                            b0, b1);
            }
        }
    }

#pragma unroll
    for (int mt = 0; mt < 4; mt++) {
#pragma unroll
        for (int rr = 0; rr < 2; rr++) {
            long row = rbase + wm * 64 + mt * 16 + g + rr * 8;
#pragma unroll
            for (int nt = 0; nt < 4; nt++) {
                int col = bn * 128 + wn * 32 + nt * 8 + t4 * 2;
                float ox = fmaxf(acc[mt][nt][rr*2+0] + bias[col    ], 0.f);
                float oy = fmaxf(acc[mt][nt][rr*2+1] + bias[col + 1], 0.f);
                *(__half2*)(C + row * DOUT + col) = __floats2half2_rn(ox, oy);
            }
        }
    }
}

// ---------------------------------------------------------------------------
// Software-pipelined persistent fused attention. 152 blocks x 256 threads,
// 1 block/SM (no reg cap -> no spills). Per block: walk tiles; while doing
// the 8-k-iter GEMM of tile j+1, run 1/8 of tile j's HardKuma epilogue per
// iteration (tensor + MUFU pipes overlap within each warp).
// 4-stage cp.async ring (stage = kk&3, compile-time after unroll).
// ---------------------------------------------------------------------------
#define Q_TILE_U32 2560   // 128 rows x 20 u32
#define K_TILE_U32 1280   // 64 rows x 20 u32
#define ATTN_SMEM_BYTES (4 * (2 * Q_TILE_U32 + 2 * K_TILE_U32) * 4)  // 122880

__global__ void __launch_bounds__(256, 1) kuma_attn_pipe_kernel(
    const unsigned short* __restrict__ Au, const unsigned short* __restrict__ Bu,
    const float* __restrict__ dist_emb, float* __restrict__ out)
{
    extern __shared__ unsigned sm[];
    unsigned* QAb = sm;                       // 4 x 2560
    unsigned* QBb = sm + 4 * Q_TILE_U32;
    unsigned* KAb = sm + 8 * Q_TILE_U32;      // 4 x 1280
    unsigned* KBb = sm + 8 * Q_TILE_U32 + 4 * K_TILE_U32;
    __shared__ float sdist[23];

    const __half* Ah = (const __half*)Au;
    const __half* Bh = (const __half*)Bu;

    int tid = threadIdx.x;
    int bx  = blockIdx.x;
    if (tid < 23) sdist[tid] = dist_emb[tid];

    int wid = tid >> 5, lane = tid & 31;
    int wm  = wid >> 1, wn = wid & 1;
    int g   = lane >> 2, t4 = lane & 3;

    int rQ0 = tid >> 2,         cQ0 = (tid & 3);
    int rQ1 = (tid + 256) >> 2, cQ1 = ((tid + 256) & 3);
    int rK = tid >> 2,          cK  = (tid & 3);

    int l7 = lane & 7, l8 = (lane >> 3) & 1, l16 = (lane >> 4) & 1;
    unsigned aoff = (unsigned)((wm * 32 + l7 + l8 * 8) * 80 + l16 * 16);
    unsigned boff = (unsigned)((wn * 32 + l7 + l16 * 8) * 80 + l8 * 16);
    unsigned qaB = (unsigned)__cvta_generic_to_shared(QAb);
    unsigned qbB = (unsigned)__cvta_generic_to_shared(QBb);
    unsigned kaB = (unsigned)__cvta_generic_to_shared(KAb);
    unsigned kbB = (unsigned)__cvta_generic_to_shared(KBb);

    int myTiles = (NTILES - bx + ATTN_GRID - 1) / ATTN_GRID;
    const int totalLi = myTiles * 8;

    float curA[2][4][4], curB[2][4][4];
    float oldA[2][4][4], oldB[2][4][4];
    int ob = 0, obt = 0, obs = 0;
    bool havOld = false;

#define PIPE_ISSUE(li) do {                                                   \
        int tl_ = (li) >> 3;                                                  \
        int tile_ = bx + tl_ * ATTN_GRID;                                     \
        int b_ = tile_ >> 9; int rem_ = tile_ & 511;                          \
        int bt_ = (rem_ >> 5) << 7; int bs_ = (rem_ & 31) << 6;               \
        const __half* qa_ = Ah + ((long)b_ * T_SEQ + bt_) * DOUT;             \
        const __half* ka_ = Ah + ((long)(8192 + b_ * T_SEQ) + bs_) * DOUT;    \
        const __half* qb_ = Bh + ((long)b_ * T_SEQ + bt_) * DOUT;             \
        const __half* kb_ = Bh + ((long)(8192 + b_ * T_SEQ) + bs_) * DOUT;    \
        int st_ = (li) & 3; int k0_ = ((li) & 7) << 5;                        \
        unsigned* QA_ = QAb + st_ * Q_TILE_U32;                               \
        unsigned* QB_ = QBb + st_ * Q_TILE_U32;                               \
        unsigned* KA_ = KAb + st_ * K_TILE_U32;                               \
        unsigned* KB_ = KBb + st_ * K_TILE_U32;                               \
        cp16(QA_ + rQ0 * 20 + cQ0 * 4, qa_ + (long)rQ0 * DOUT + k0_ + cQ0 * 8); \
        cp16(QA_ + rQ1 * 20 + cQ1 * 4, qa_ + (long)rQ1 * DOUT + k0_ + cQ1 * 8); \
        cp16(QB_ + rQ0 * 20 + cQ0 * 4, qb_ + (long)rQ0 * DOUT + k0_ + cQ0 * 8); \
        cp16(QB_ + rQ1 * 20 + cQ1 * 4, qb_ + (long)rQ1 * DOUT + k0_ + cQ1 * 8); \
        cp16(KA_ + rK * 20 + cK * 4, ka_ + (long)rK * DOUT + k0_ + cK * 8);     \
        cp16(KB_ + rK * 20 + cK * 4, kb_ + (long)rK * DOUT + k0_ + cK * 8);     \
    } while (0)

// one epilogue output pair (idx selects fragment slot) from OLD tile
#define EPI_IDX(IDX) do {                                                     \
        int mt_ = (IDX) >> 3, rr_ = ((IDX) >> 2) & 1, nt_ = (IDX) & 3;        \
        int trow_ = obt + wm * 32 + mt_ * 16 + g + rr_ * 8;                   \
        int scol_ = obs + wn * 32 + nt_ * 8 + t4 * 2;                         \
        int rel0_ = max(-11, min(11, scol_     - trow_)) + 11;                \
        int rel1_ = max(-11, min(11, scol_ + 1 - trow_)) + 11;                \
        float rd0_ = sdist[rel0_], rd1_ = sdist[rel1_];                       \
        float2 o_;                                                            \
        o_.x = kuma_out(oldA[mt_][nt_][rr_*2+0] + rd0_,                       \
                        oldB[mt_][nt_][rr_*2+0] + rd0_);                      \
        o_.y = kuma_out(oldA[mt_][nt_][rr_*2+1] + rd1_,                       \
                        oldB[mt_][nt_][rr_*2+1] + rd1_);                      \
        *(float2*)(out + ((long)ob * T_SEQ + trow_) * T_SEQ + scol_) = o_;    \
    } while (0)

    PIPE_ISSUE(0); cp_commit();
    PIPE_ISSUE(1); cp_commit();

    int li = 0;
    for (int tl = 0; tl < myTiles; tl++) {
        int tile = bx + tl * ATTN_GRID;
        int cb = tile >> 9; int rem = tile & 511;
        int cbt = (rem >> 5) << 7; int cbs = (rem & 31) << 6;

#pragma unroll
        for (int mt = 0; mt < 2; mt++)
#pragma unroll
            for (int nt = 0; nt < 4; nt++)
#pragma unroll
                for (int c = 0; c < 4; c++) { curA[mt][nt][c] = 0.f; curB[mt][nt][c] = 0.f; }

#pragma unroll
        for (int kk = 0; kk < 8; kk++) {
            cp_wait<1>();
            __syncthreads();
            if (li + 2 < totalLi) PIPE_ISSUE(li + 2);
            cp_commit();

            int st = kk & 3;
            unsigned qaS = qaB + st * (Q_TILE_U32 * 4);
            unsigned qbS = qbB + st * (Q_TILE_U32 * 4);
            unsigned kaS = kaB + st * (K_TILE_U32 * 4);
            unsigned kbS = kbB + st * (K_TILE_U32 * 4);

#pragma unroll
            for (int k16 = 0; k16 < 2; k16++) {
                unsigned kbyt = k16 * 32;
                unsigned qaf[2][4], qbf[2][4], kaf[2][4], kbf[2][4];
#pragma unroll
                for (int mt = 0; mt < 2; mt++) {
                    ldsm_x4(qaf[mt][0], qaf[mt][1], qaf[mt][2], qaf[mt][3],
                            qaS + aoff + mt * 1280 + kbyt);
                    ldsm_x4(qbf[mt][0], qbf[mt][1], qbf[mt][2], qbf[mt][3],
                            qbS + aoff + mt * 1280 + kbyt);
                }
#pragma unroll
                for (int ntp = 0; ntp < 2; ntp++) {
                    ldsm_x4(kaf[ntp][0], kaf[ntp][1], kaf[ntp][2], kaf[ntp][3],
                            kaS + boff + ntp * 1280 + kbyt);
                    ldsm_x4(kbf[ntp][0], kbf[ntp][1], kbf[ntp][2], kbf[ntp][3],
                            kbS + boff + ntp * 1280 + kbyt);
                }
#pragma unroll
                for (int nt = 0; nt < 4; nt++) {
                    unsigned bA0 = kaf[nt >> 1][(nt & 1) * 2];
                    unsigned bA1 = kaf[nt >> 1][(nt & 1) * 2 + 1];
                    unsigned bB0 = kbf[nt >> 1][(nt & 1) * 2];
                    unsigned bB1 = kbf[nt >> 1][(nt & 1) * 2 + 1];
#pragma unroll
                    for (int mt = 0; mt < 2; mt++) {
                        mma_f16(curA[mt][nt][0], curA[mt][nt][1],
                                curA[mt][nt][2], curA[mt][nt][3],
                                qaf[mt][0], qaf[mt][1], qaf[mt][2], qaf[mt][3],
                                bA0, bA1);
                        mma_f16(curB[mt][nt][0], curB[mt][nt][1],
                                curB[mt][nt][2], curB[mt][nt][3],
                                qbf[mt][0], qbf[mt][1], qbf[mt][2], qbf[mt][3],
                                bB0, bB1);
                    }
                }
            }

            // 1/8 of previous tile's epilogue (tensor + MUFU pipe overlap)
            if (havOld) {
                EPI_IDX(kk * 2);
                EPI_IDX(kk * 2 + 1);
            }
            li++;
        }

        // retire cur -> old
#pragma unroll
        for (int mt = 0; mt < 2; mt++)
#pragma unroll
            for (int nt = 0; nt < 4; nt++)
#pragma unroll
                for (int c = 0; c < 4; c++) {
                    oldA[mt][nt][c] = curA[mt][nt][c];
                    oldB[mt][nt][c] = curB[mt][nt][c];
                }
        ob = cb; obt = cbt; obs = cbs;
        havOld = true;
    }

    // drain: final tile's epilogue
    if (havOld) {
#pragma unroll
        for (int kk = 0; kk < 8; kk++) {
            EPI_IDX(kk * 2);
            EPI_IDX(kk * 2 + 1);
        }
    }
}

// ---------------------------------------------------------------------------
extern "C" void kernel_launch(void* const* d_in, const int* in_sizes, int n_in,
                              void* d_out, int out_size)
{
    const float* q    = (const float*)d_in[0];
    const float* k    = (const float*)d_in[1];
    const float* Wa1  = (const float*)d_in[2];
    const float* ba1  = (const float*)d_in[3];
    const float* Wa2  = (const float*)d_in[4];
    const float* ba2  = (const float*)d_in[5];
    const float* Wb1  = (const float*)d_in[6];
    const float* bb1  = (const float*)d_in[7];
    const float* Wb2  = (const float*)d_in[8];
    const float* bb2  = (const float*)d_in[9];
    const float* dist = (const float*)d_in[10];
    float* out = (float*)d_out;

    unsigned short *X16, *h1, *h2, *Ah, *Bh, *t1a, *t1b, *t2a, *t2b;
    cudaGetSymbolAddress((void**)&X16, g_X16);
    cudaGetSymbolAddress((void**)&h1,  g_h1);
    cudaGetSymbolAddress((void**)&h2,  g_h2);
    cudaGetSymbolAddress((void**)&Ah,  g_A);
    cudaGetSymbolAddress((void**)&Bh,  g_B);
    cudaGetSymbolAddress((void**)&t1a, g_Wt1a);
    cudaGetSymbolAddress((void**)&t1b, g_Wt1b);
    cudaGetSymbolAddress((void**)&t2a, g_Wt2a);
    cudaGetSymbolAddress((void**)&t2b, g_Wt2b);

    cudaFuncSetAttribute(mlp_f16_kernel,
        cudaFuncAttributeMaxDynamicSharedMemorySize, MLPH_SMEM_BYTES);
    cudaFuncSetAttribute(kuma_attn_pipe_kernel,
        cudaFuncAttributeMaxDynamicSharedMemorySize, ATTN_SMEM_BYTES);

    prep_kernel<<<CVT_BLOCKS + 512, 256>>>(
        q, k, (__half*)X16,
        Wa1, Wb1, Wa2, Wb2,
        (__half*)t1a, (__half*)t1b, (__half*)t2a, (__half*)t2b);

    dim3 g1(4, 128);
    mlp_f16_kernel<<<g1, 256, MLPH_SMEM_BYTES>>>(
        (const __half*)X16, (const __half*)t1a, ba1, (__half*)h1,
        (const __half*)X16, (const __half*)t1b, bb1, (__half*)h2, DIN);
    mlp_f16_kernel<<<g1, 256, MLPH_SMEM_BYTES>>>(
        (const __half*)h1, (const __half*)t2a, ba2, (__half*)Ah,
        (const __half*)h2, (const __half*)t2b, bb2, (__half*)Bh, DOUT);

    kuma_attn_pipe_kernel<<<ATTN_GRID, 256, ATTN_SMEM_BYTES>>>(Ah, Bh, dist, out);
}

// round 16
// speedup vs baseline: 1.2832x; 1.2832x over previous
#include <cuda_runtime.h>
#include <cuda_fp16.h>

#define T_SEQ 2048
#define BATCH 4
#define DIN   512
#define DOUT  256
#define NROWS 16384   // 2*BATCH*T_SEQ (q rows then k rows)

// Scratch (static __device__ — no allocation)
__device__ unsigned short g_h1[NROWS * DOUT];   // fp16 hidden (a)
__device__ unsigned short g_h2[NROWS * DOUT];   // fp16 hidden (b)
__device__ unsigned short g_A[NROWS * DOUT];    // fp16 a-branch MLP out
__device__ unsigned short g_B[NROWS * DOUT];    // fp16 b-branch MLP out
__device__ unsigned short g_Wt1a[DOUT * DIN];
__device__ unsigned short g_Wt1b[DOUT * DIN];
__device__ unsigned short g_Wt2a[DOUT * DOUT];
__device__ unsigned short g_Wt2b[DOUT * DOUT];

// ---------------------------------------------------------------------------
// helpers
// ---------------------------------------------------------------------------
__device__ __forceinline__ float f_ex2(float x) {
    float y; asm("ex2.approx.ftz.f32 %0, %1;" : "=f"(y) : "f"(x)); return y;
}
__device__ __forceinline__ float f_lg2(float x) {
    float y; asm("lg2.approx.ftz.f32 %0, %1;" : "=f"(y) : "f"(x)); return y;
}
__device__ __forceinline__ float f_rcp(float x) {
    float y; asm("rcp.approx.ftz.f32 %0, %1;" : "=f"(y) : "f"(x)); return y;
}
__device__ __forceinline__ void mma_f16(
    float& c0, float& c1, float& c2, float& c3,
    unsigned a0, unsigned a1, unsigned a2, unsigned a3,
    unsigned b0, unsigned b1)
{
    asm("mma.sync.aligned.m16n8k16.row.col.f32.f16.f16.f32 "
        "{%0,%1,%2,%3}, {%4,%5,%6,%7}, {%8,%9}, {%0,%1,%2,%3};"
        : "+f"(c0), "+f"(c1), "+f"(c2), "+f"(c3)
        : "r"(a0), "r"(a1), "r"(a2), "r"(a3), "r"(b0), "r"(b1));
}
__device__ __forceinline__ void ldsm_x4(unsigned& r0, unsigned& r1,
                                        unsigned& r2, unsigned& r3, unsigned a) {
    asm volatile("ldmatrix.sync.aligned.m8n8.x4.shared.b16 {%0,%1,%2,%3}, [%4];"
                 : "=r"(r0), "=r"(r1), "=r"(r2), "=r"(r3) : "r"(a));
}
__device__ __forceinline__ void cp16(void* d, const void* s) {
    unsigned a = (unsigned)__cvta_generic_to_shared(d);
    asm volatile("cp.async.cg.shared.global [%0], [%1], 16;" :: "r"(a), "l"(s));
}
__device__ __forceinline__ void cp_commit() {
    asm volatile("cp.async.commit_group;");
}
template<int N> __device__ __forceinline__ void cp_wait() {
    asm volatile("cp.async.wait_group %0;" :: "n"(N));
}

#define LN2   0.69314718056f
#define RLN2  1.44269504089f

__device__ __forceinline__ float softplus_fast(float x) {
    float e = f_ex2(-fabsf(x) * RLN2);
    return fmaxf(x, 0.f) + f_lg2(1.f + e) * LN2;
}

// HardKuma epilogue, fused-Stirling Beta
__device__ __forceinline__ float kuma_out(float ar, float br) {
    const float K_T0 = -3.58496250072f;   // log2(1/12)
    const float K_T1 = -0.12553088208f;   // log2(11/12)
    float a  = fminf(fmaxf(softplus_fast(ar), 0.01f), 100.f);
    float bb = fminf(fmaxf(softplus_fast(br), 0.01f), 100.f);
    float u0 = f_ex2(a * K_T0);
    float u1 = f_ex2(a * K_T1);
    float E0 = f_ex2(bb * f_lg2(1.f - u0));  // 1 - p0
    float p1 = f_ex2(bb * f_lg2(1.f - u1));
    float pc = E0 - p1;

    float g  = 1.f + f_rcp(a);
    float s  = g + bb;
    float y1 = g + 4.f, y2 = bb + 4.f, y3 = s + 4.f;
    float L1 = f_lg2(y1), L2 = f_lg2(y2), L3 = f_lg2(y3);
    float pg = g  * (g  + 1.f) * (g  + 2.f) * (g  + 3.f);
    float pb = bb * (bb + 1.f) * (bb + 2.f) * (bb + 3.f);
    float ps = s  * (s  + 1.f) * (s  + 2.f) * (s  + 3.f);
    float pgb = pg * pb;
    float d3  = y1 * y2 * y3;
    float inv = f_rcp(d3 * pgb);
    float n   = fmaf(y1, y3, fmaf(y2, y3, -y1 * y2));
    float c   = 0.08333333333f * (n * pgb) * inv;
    float R   = ps * d3 * inv;
    float lm2 = (y1 - 0.5f) * L1 + (y2 - 0.5f) * L2 - (y3 - 0.5f) * L3
              + (c - 3.08106146679f) * RLN2;
    float mean = bb * R * f_ex2(lm2);
    mean = fminf(fmaxf(fmaf(1.2f, mean, -0.1f), 0.f), 1.f);

    float zo = (1.f - E0 > p1) ? 0.f : 1.f;
    return (pc < 0.5f) ? zo : mean;
}

// ---------------------------------------------------------------------------
// Weight transpose + fp16 convert only (q/k conversion folded into mlp1).
// grid = 512 x 256 threads.
// ---------------------------------------------------------------------------
__global__ void prep_w_kernel(
    const float* __restrict__ Wa1, const float* __restrict__ Wb1,
    const float* __restrict__ Wa2, const float* __restrict__ Wb2,
    __half* __restrict__ T1a, __half* __restrict__ T1b,
    __half* __restrict__ T2a, __half* __restrict__ T2b)
{
    __shared__ float t[32][33];
    int idx = blockIdx.x;                 // [0, 512)
    int z  = idx >> 7;
    int rem = idx & 127;
    int gy = rem >> 4, gx = rem & 15;
    int K = (z < 2) ? DIN : DOUT;
    if (gx * 32 >= K) return;
    const float* S = (z == 0) ? Wa1 : (z == 1) ? Wb1 : (z == 2) ? Wa2 : Wb2;
    __half*      D = (z == 0) ? T1a : (z == 1) ? T1b : (z == 2) ? T2a : T2b;

    int kb = gx * 32, nb = gy * 32;
    int tid = threadIdx.x;
    int x = tid & 31, y = tid >> 5;       // 32 x 8
#pragma unroll
    for (int i = 0; i < 32; i += 8)
        t[y + i][x] = S[(long)(kb + y + i) * DOUT + nb + x];
    __syncthreads();
#pragma unroll
    for (int i = 0; i < 32; i += 8)
        D[(long)(nb + y + i) * K + kb + x] = __float2half(t[x][y + i]);
}

// ---------------------------------------------------------------------------
// fp16 MLP GEMM, cp.async 4-stage (weights), ldmatrix + mma.m16n8k16.
// FP32IN=1: X is fp32 (q/k), converted in-register two stages ahead and
// stored to smem as fp16 (eliminates the separate conversion pass).
// FP32IN=0: X is fp16, loaded via cp.async like weights.
// grid = (4, 128). Block tile 128x128, warps 2(m)x4(n), warp tile 64x32.
// ---------------------------------------------------------------------------
#define MLPH_TILE_U32 2560
#define MLPH_SMEM_BYTES (4 * 2 * MLPH_TILE_U32 * 4)   // 81920

template<int FP32IN>
__global__ void __launch_bounds__(256, 2) mlp_f16_kernel(
    const void* __restrict__ X1v, const __half* __restrict__ Wt1,
    const float* __restrict__ bias1, __half* __restrict__ C1,
    const void* __restrict__ X2v, const __half* __restrict__ Wt2,
    const float* __restrict__ bias2, __half* __restrict__ C2,
    int K)
{
    extern __shared__ unsigned sm[];
    unsigned* ASb = sm;
    unsigned* BSb = sm + 4 * MLPH_TILE_U32;

    int set = blockIdx.x >> 1;
    int bn  = blockIdx.x & 1;
    long rbase = (long)blockIdx.y * 128;

    const void*   Xv   = set ? X2v : X1v;
    const __half* Wb   = (set ? Wt2 : Wt1) + (long)(bn * 128) * K;
    const float*  bias = set ? bias2 : bias1;
    __half*       C    = set ? C2  : C1;

    const float*  Xf = (const float*)Xv + rbase * K;   // FP32IN path
    const __half* Xh = (const __half*)Xv + rbase * K;  // fp16 path

    int tid = threadIdx.x;
    int wid = tid >> 5, lane = tid & 31;
    int wm  = wid >> 2, wn = wid & 3;
    int g   = lane >> 2, t4 = lane & 3;

    int r0 = tid >> 2,          c0 = tid & 3;
    int r1 = (tid + 256) >> 2,  c1 = (tid + 256) & 3;

    int l7 = lane & 7, l8 = (lane >> 3) & 1, l16 = (lane >> 4) & 1;
    unsigned aoff = (unsigned)((wm * 64 + l7 + l8 * 8) * 80 + l16 * 16);
    unsigned boff = (unsigned)((wn * 32 + l7 + l16 * 8) * 80 + l8 * 16);
    unsigned aBase = (unsigned)__cvta_generic_to_shared(ASb);
    unsigned bBase = (unsigned)__cvta_generic_to_shared(BSb);

    float acc[4][4][4];
#pragma unroll
    for (int mt = 0; mt < 4; mt++)
#pragma unroll
        for (int nt = 0; nt < 4; nt++)
#pragma unroll
            for (int c = 0; c < 4; c++) acc[mt][nt][c] = 0.f;

    const int ITERS = K >> 5;

    // staging regs for FP32IN path (2 chunks x 8 floats)
    float4 xa0, xb0, xa1, xb1;

#define W_ISSUE(ki) do {                                                      \
        int st_ = (ki) & 3; int k0_ = (ki) << 5;                              \
        unsigned* B_ = BSb + st_ * MLPH_TILE_U32;                             \
        cp16(B_ + r0 * 20 + c0 * 4, Wb + (long)r0 * K + k0_ + c0 * 8);        \
        cp16(B_ + r1 * 20 + c1 * 4, Wb + (long)r1 * K + k0_ + c1 * 8);        \
    } while (0)

#define X_ISSUE_H(ki) do {                                                    \
        int st_ = (ki) & 3; int k0_ = (ki) << 5;                              \
        unsigned* A_ = ASb + st_ * MLPH_TILE_U32;                             \
        cp16(A_ + r0 * 20 + c0 * 4, Xh + (long)r0 * K + k0_ + c0 * 8);        \
        cp16(A_ + r1 * 20 + c1 * 4, Xh + (long)r1 * K + k0_ + c1 * 8);        \
    } while (0)

#define X_LOAD_F(ki) do {                                                     \
        int k0_ = (ki) << 5;                                                  \
        const float* p0_ = Xf + (long)r0 * K + k0_ + c0 * 8;                  \
        const float* p1_ = Xf + (long)r1 * K + k0_ + c1 * 8;                  \
        xa0 = *(const float4*)p0_;  xb0 = *(const float4*)(p0_ + 4);          \
        xa1 = *(const float4*)p1_;  xb1 = *(const float4*)(p1_ + 4);          \
    } while (0)

#define X_STORE_F(ki) do {                                                    \
        int st_ = (ki) & 3;                                                   \
        unsigned* A_ = ASb + st_ * MLPH_TILE_U32;                             \
        __half2 h_[4];                                                        \
        h_[0] = __floats2half2_rn(xa0.x, xa0.y);                              \
        h_[1] = __floats2half2_rn(xa0.z, xa0.w);                              \
        h_[2] = __floats2half2_rn(xb0.x, xb0.y);                              \
        h_[3] = __floats2half2_rn(xb0.z, xb0.w);                              \
        *(uint4*)(A_ + r0 * 20 + c0 * 4) = *(uint4*)h_;                       \
        h_[0] = __floats2half2_rn(xa1.x, xa1.y);                              \
        h_[1] = __floats2half2_rn(xa1.z, xa1.w);                              \
        h_[2] = __floats2half2_rn(xb1.x, xb1.y);                              \
        h_[3] = __floats2half2_rn(xb1.z, xb1.w);                              \
        *(uint4*)(A_ + r1 * 20 + c1 * 4) = *(uint4*)h_;                       \
    } while (0)

    if (FP32IN) {
        X_LOAD_F(0); X_STORE_F(0);
        X_LOAD_F(1); X_STORE_F(1);
        W_ISSUE(0); cp_commit();
        W_ISSUE(1); cp_commit();
        W_ISSUE(2); cp_commit();
    } else {
        X_ISSUE_H(0); W_ISSUE(0); cp_commit();
        X_ISSUE_H(1); W_ISSUE(1); cp_commit();
        X_ISSUE_H(2); W_ISSUE(2); cp_commit();
    }

    for (int it = 0; it < ITERS; it++) {
        cp_wait<2>();
        __syncthreads();
        if (it + 3 < ITERS) W_ISSUE(it + 3);
        if (!FP32IN) { if (it + 3 < ITERS) X_ISSUE_H(it + 3); }
        cp_commit();
        if (FP32IN) { if (it + 2 < ITERS) X_LOAD_F(it + 2); }

        int st = it & 3;
        unsigned aS = aBase + st * (MLPH_TILE_U32 * 4);
        unsigned bS = bBase + st * (MLPH_TILE_U32 * 4);

#pragma unroll
        for (int k16 = 0; k16 < 2; k16++) {
            unsigned kbyt = k16 * 32;
            unsigned af[4][4], bf[2][4];
#pragma unroll
            for (int mt = 0; mt < 4; mt++)
                ldsm_x4(af[mt][0], af[mt][1], af[mt][2], af[mt][3],
                        aS + aoff + mt * 1280 + kbyt);
#pragma unroll
            for (int ntp = 0; ntp < 2; ntp++)
                ldsm_x4(bf[ntp][0], bf[ntp][1], bf[ntp][2], bf[ntp][3],
                        bS + boff + ntp * 1280 + kbyt);
#pragma unroll
            for (int nt = 0; nt < 4; nt++) {
                unsigned b0 = bf[nt >> 1][(nt & 1) * 2];
                unsigned b1 = bf[nt >> 1][(nt & 1) * 2 + 1];
#pragma unroll
                for (int mt = 0; mt < 4; mt++)
                    mma_f16(acc[mt][nt][0], acc[mt][nt][1],
                            acc[mt][nt][2], acc[mt][nt][3],
                            af[mt][0], af[mt][1], af[mt][2], af[mt][3],
                            b0, b1);
            }
        }

        if (FP32IN) { if (it + 2 < ITERS) X_STORE_F(it + 2); }
    }

    // epilogue: bias + relu, fp16 out
#pragma unroll
    for (int mt = 0; mt < 4; mt++) {
#pragma unroll
        for (int rr = 0; rr < 2; rr++) {
            long row = rbase + wm * 64 + mt * 16 + g + rr * 8;
#pragma unroll
            for (int nt = 0; nt < 4; nt++) {
                int col = bn * 128 + wn * 32 + nt * 8 + t4 * 2;
                float ox = fmaxf(acc[mt][nt][rr*2+0] + bias[col    ], 0.f);
                float oy = fmaxf(acc[mt][nt][rr*2+1] + bias[col + 1], 0.f);
                *(__half2*)(C + row * DOUT + col) = __floats2half2_rn(ox, oy);
            }
        }
    }
}

// ---------------------------------------------------------------------------
// Layer-1 X selector: rows < 8192 -> q, else k. Done with two grid halves:
// launched as one kernel over the q|k concatenation by passing q and k and
// picking per block row base. To keep the template simple we pre-split:
// blocks with rbase < 8192 read q, others read k (same kernel, pointer math).
// Implemented via a tiny wrapper kernel parameterization below: we pass
// Xq for set pointers and fix up inside. Simplest: two sub-launches share
// the grid via blockIdx.y splitting — rbase >= 8192 uses k.
// (handled in kernel_launch by passing q and k as X1v/X2v of two launches)
// ---------------------------------------------------------------------------

// fp16 fused score GEMM (a & b) + HardKuma epilogue — R13 config (best).
#define Q_TILE_U32 2560
#define K_TILE_U32 1280
#define ATTN_SMEM_BYTES (3 * (2 * Q_TILE_U32 + 2 * K_TILE_U32) * 4)

__global__ void __launch_bounds__(256, 2) kuma_attn_f16_kernel(
    const unsigned short* __restrict__ Au, const unsigned short* __restrict__ Bu,
    const float* __restrict__ dist_emb, float* __restrict__ out)
{
    extern __shared__ unsigned sm[];
    unsigned* QAb = sm;
    unsigned* QBb = sm + 3 * Q_TILE_U32;
    unsigned* KAb = sm + 6 * Q_TILE_U32;
    unsigned* KBb = sm + 6 * Q_TILE_U32 + 3 * K_TILE_U32;
    __shared__ float sdist[23];

    const __half* Ah = (const __half*)Au;
    const __half* Bh = (const __half*)Bu;

    int b  = blockIdx.z;
    int bt = blockIdx.y * 128;
    int bs = blockIdx.x * 64;
    int tid = threadIdx.x;
    if (tid < 23) sdist[tid] = dist_emb[tid];

    int wid = tid >> 5, lane = tid & 31;
    int wm  = wid >> 1, wn = wid & 1;
    int g   = lane >> 2, t4 = lane & 3;

    const __half* qa = Ah + ((long)b * T_SEQ + bt) * DOUT;
    const __half* ka = Ah + ((long)(8192 + b * T_SEQ) + bs) * DOUT;
    const __half* qb = Bh + ((long)b * T_SEQ + bt) * DOUT;
    const __half* kb = Bh + ((long)(8192 + b * T_SEQ) + bs) * DOUT;

    int rQ0 = tid >> 2,         cQ0 = (tid & 3);
    int rQ1 = (tid + 256) >> 2, cQ1 = ((tid + 256) & 3);
    int rK = tid >> 2,          cK  = (tid & 3);

    int l7 = lane & 7, l8 = (lane >> 3) & 1, l16 = (lane >> 4) & 1;
    unsigned aoff = (unsigned)((wm * 32 + l7 + l8 * 8) * 80 + l16 * 16);
    unsigned boff = (unsigned)((wn * 32 + l7 + l16 * 8) * 80 + l8 * 16);
    unsigned qaB = (unsigned)__cvta_generic_to_shared(QAb);
    unsigned qbB = (unsigned)__cvta_generic_to_shared(QBb);
    unsigned kaB = (unsigned)__cvta_generic_to_shared(KAb);
    unsigned kbB = (unsigned)__cvta_generic_to_shared(KBb);

    float accA[2][4][4], accB[2][4][4];
#pragma unroll
    for (int mt = 0; mt < 2; mt++)
#pragma unroll
        for (int nt = 0; nt < 4; nt++)
#pragma unroll
            for (int c = 0; c < 4; c++) { accA[mt][nt][c] = 0.f; accB[mt][nt][c] = 0.f; }

    const int ITERS = DOUT >> 5;   // 8

#define ATTN_ISSUE(ki) do {                                                   \
        int st_ = (ki) % 3; int k0_ = (ki) << 5;                              \
        unsigned* QA_ = QAb + st_ * Q_TILE_U32;                               \
        unsigned* QB_ = QBb + st_ * Q_TILE_U32;                               \
        unsigned* KA_ = KAb + st_ * K_TILE_U32;                               \
        unsigned* KB_ = KBb + st_ * K_TILE_U32;                               \
        cp16(QA_ + rQ0 * 20 + cQ0 * 4, qa + (long)rQ0 * DOUT + k0_ + cQ0 * 8);\
        cp16(QA_ + rQ1 * 20 + cQ1 * 4, qa + (long)rQ1 * DOUT + k0_ + cQ1 * 8);\
        cp16(QB_ + rQ0 * 20 + cQ0 * 4, qb + (long)rQ0 * DOUT + k0_ + cQ0 * 8);\
        cp16(QB_ + rQ1 * 20 + cQ1 * 4, qb + (long)rQ1 * DOUT + k0_ + cQ1 * 8);\
        cp16(KA_ + rK * 20 + cK * 4, ka + (long)rK * DOUT + k0_ + cK * 8);    \
        cp16(KB_ + rK * 20 + cK * 4, kb + (long)rK * DOUT + k0_ + cK * 8);    \
    } while (0)

    ATTN_ISSUE(0); cp_commit();
    ATTN_ISSUE(1); cp_commit();

    for (int it = 0; it < ITERS; it++) {
        cp_wait<1>();
        __syncthreads();
        if (it + 2 < ITERS) ATTN_ISSUE(it + 2);
        cp_commit();

        int st = it % 3;
        unsigned qaS = qaB + st * (Q_TILE_U32 * 4);
        unsigned qbS = qbB + st * (Q_TILE_U32 * 4);
        unsigned kaS = kaB + st * (K_TILE_U32 * 4);
        unsigned kbS = kbB + st * (K_TILE_U32 * 4);

#pragma unroll
        for (int k16 = 0; k16 < 2; k16++) {
            unsigned kbyt = k16 * 32;
            unsigned qaf[2][4], qbf[2][4], kaf[2][4], kbf[2][4];
#pragma unroll
            for (int mt = 0; mt < 2; mt++) {
                ldsm_x4(qaf[mt][0], qaf[mt][1], qaf[mt][2], qaf[mt][3],
                        qaS + aoff + mt * 1280 + kbyt);
                ldsm_x4(qbf[mt][0], qbf[mt][1], qbf[mt][2], qbf[mt][3],
                        qbS + aoff + mt * 1280 + kbyt);
            }
#pragma unroll
            for (int ntp = 0; ntp < 2; ntp++) {
                ldsm_x4(kaf[ntp][0], kaf[ntp][1], kaf[ntp][2], kaf[ntp][3],
                        kaS + boff + ntp * 1280 + kbyt);
                ldsm_x4(kbf[ntp][0], kbf[ntp][1], kbf[ntp][2], kbf[ntp][3],
                        kbS + boff + ntp * 1280 + kbyt);
            }
#pragma unroll
            for (int nt = 0; nt < 4; nt++) {
                unsigned bA0 = kaf[nt >> 1][(nt & 1) * 2];
                unsigned bA1 = kaf[nt >> 1][(nt & 1) * 2 + 1];
                unsigned bB0 = kbf[nt >> 1][(nt & 1) * 2];
                unsigned bB1 = kbf[nt >> 1][(nt & 1) * 2 + 1];
#pragma unroll
                for (int mt = 0; mt < 2; mt++) {
                    mma_f16(accA[mt][nt][0], accA[mt][nt][1],
                            accA[mt][nt][2], accA[mt][nt][3],
                            qaf[mt][0], qaf[mt][1], qaf[mt][2], qaf[mt][3],
                            bA0, bA1);
                    mma_f16(accB[mt][nt][0], accB[mt][nt][1],
                            accB[mt][nt][2], accB[mt][nt][3],
                            qbf[mt][0], qbf[mt][1], qbf[mt][2], qbf[mt][3],
                            bB0, bB1);
                }
            }
        }
    }

    // HardKuma epilogue + store
#pragma unroll
    for (int mt = 0; mt < 2; mt++) {
#pragma unroll
        for (int rr = 0; rr < 2; rr++) {
            int trow = bt + wm * 32 + mt * 16 + g + rr * 8;
#pragma unroll
            for (int nt = 0; nt < 4; nt++) {
                int scol = bs + wn * 32 + nt * 8 + t4 * 2;
                int rel0 = max(-11, min(11, scol     - trow)) + 11;
                int rel1 = max(-11, min(11, scol + 1 - trow)) + 11;
                float rd0 = sdist[rel0], rd1 = sdist[rel1];
                float2 o;
                o.x = kuma_out(accA[mt][nt][rr*2+0] + rd0, accB[mt][nt][rr*2+0] + rd0);
                o.y = kuma_out(accA[mt][nt][rr*2+1] + rd1, accB[mt][nt][rr*2+1] + rd1);
                *(float2*)(out + ((long)b * T_SEQ + trow) * T_SEQ + scol) = o;
            }
        }
    }
}

// ---------------------------------------------------------------------------
extern "C" void kernel_launch(void* const* d_in, const int* in_sizes, int n_in,
                              void* d_out, int out_size)
{
    const float* q    = (const float*)d_in[0];
    const float* k    = (const float*)d_in[1];
    const float* Wa1  = (const float*)d_in[2];
    const float* ba1  = (const float*)d_in[3];
    const float* Wa2  = (const float*)d_in[4];
    const float* ba2  = (const float*)d_in[5];
    const float* Wb1  = (const float*)d_in[6];
    const float* bb1  = (const float*)d_in[7];
    const float* Wb2  = (const float*)d_in[8];
    const float* bb2  = (const float*)d_in[9];
    const float* dist = (const float*)d_in[10];
    float* out = (float*)d_out;

    unsigned short *h1, *h2, *Ah, *Bh, *t1a, *t1b, *t2a, *t2b;
    cudaGetSymbolAddress((void**)&h1,  g_h1);
    cudaGetSymbolAddress((void**)&h2,  g_h2);
    cudaGetSymbolAddress((void**)&Ah,  g_A);
    cudaGetSymbolAddress((void**)&Bh,  g_B);
    cudaGetSymbolAddress((void**)&t1a, g_Wt1a);
    cudaGetSymbolAddress((void**)&t1b, g_Wt1b);
    cudaGetSymbolAddress((void**)&t2a, g_Wt2a);
    cudaGetSymbolAddress((void**)&t2b, g_Wt2b);

    cudaFuncSetAttribute(mlp_f16_kernel<0>,
        cudaFuncAttributeMaxDynamicSharedMemorySize, MLPH_SMEM_BYTES);
    cudaFuncSetAttribute(mlp_f16_kernel<1>,
        cudaFuncAttributeMaxDynamicSharedMemorySize, MLPH_SMEM_BYTES);
    cudaFuncSetAttribute(kuma_attn_f16_kernel,
        cudaFuncAttributeMaxDynamicSharedMemorySize, ATTN_SMEM_BYTES);

    prep_w_kernel<<<512, 256>>>(Wa1, Wb1, Wa2, Wb2,
        (__half*)t1a, (__half*)t1b, (__half*)t2a, (__half*)t2b);

    // layer 1: q rows (blockIdx.y 0-63), k rows (64-127) — split into two
    // launches over the row halves so each reads the right fp32 source.
    dim3 g1q(4, 64), g1k(4, 64);
    // q half: rows [0, 8192)
    mlp_f16_kernel<1><<<g1q, 256, MLPH_SMEM_BYTES>>>(
        (const void*)q, (const __half*)t1a, ba1, (__half*)h1,
        (const void*)q, (const __half*)t1b, bb1, (__half*)h2, DIN);
    // k half: rows [8192, 16384) — output offset by 8192 rows
    mlp_f16_kernel<1><<<g1k, 256, MLPH_SMEM_BYTES>>>(
        (const void*)k, (const __half*)t1a, ba1, (__half*)(h1 + 8192L * DOUT),
        (const void*)k, (const __half*)t1b, bb1, (__half*)(h2 + 8192L * DOUT), DIN);

    dim3 g1(4, 128);
    mlp_f16_kernel<0><<<g1, 256, MLPH_SMEM_BYTES>>>(
        (const void*)h1, (const __half*)t2a, ba2, (__half*)Ah,
        (const void*)h2, (const __half*)t2b, bb2, (__half*)Bh, DOUT);

    dim3 g2(T_SEQ / 64, T_SEQ / 128, BATCH);
    kuma_attn_f16_kernel<<<g2, 256, ATTN_SMEM_BYTES>>>(Ah, Bh, dist, out);
}

// round 17
// speedup vs baseline: 1.3056x; 1.0175x over previous
#include <cuda_runtime.h>
#include <cuda_fp16.h>

#define T_SEQ 2048
#define BATCH 4
#define DIN   512
#define DOUT  256
#define NROWS 16384   // 2*BATCH*T_SEQ (q rows then k rows)

// Scratch (static __device__ — no allocation)
__device__ unsigned short g_h1[NROWS * DOUT];   // fp16 hidden (a)
__device__ unsigned short g_h2[NROWS * DOUT];   // fp16 hidden (b)
__device__ unsigned short g_A[NROWS * DOUT];    // fp16 a-branch MLP out
__device__ unsigned short g_B[NROWS * DOUT];    // fp16 b-branch MLP out
__device__ unsigned short g_Wt1a[DOUT * DIN];
__device__ unsigned short g_Wt1b[DOUT * DIN];
__device__ unsigned short g_Wt2a[DOUT * DOUT];
__device__ unsigned short g_Wt2b[DOUT * DOUT];

// ---------------------------------------------------------------------------
// helpers
// ---------------------------------------------------------------------------
__device__ __forceinline__ float f_ex2(float x) {
    float y; asm("ex2.approx.ftz.f32 %0, %1;" : "=f"(y) : "f"(x)); return y;
}
__device__ __forceinline__ float f_lg2(float x) {
    float y; asm("lg2.approx.ftz.f32 %0, %1;" : "=f"(y) : "f"(x)); return y;
}
__device__ __forceinline__ float f_rcp(float x) {
    float y; asm("rcp.approx.ftz.f32 %0, %1;" : "=f"(y) : "f"(x)); return y;
}
__device__ __forceinline__ void mma_f16(
    float& c0, float& c1, float& c2, float& c3,
    unsigned a0, unsigned a1, unsigned a2, unsigned a3,
    unsigned b0, unsigned b1)
{
    asm("mma.sync.aligned.m16n8k16.row.col.f32.f16.f16.f32 "
        "{%0,%1,%2,%3}, {%4,%5,%6,%7}, {%8,%9}, {%0,%1,%2,%3};"
        : "+f"(c0), "+f"(c1), "+f"(c2), "+f"(c3)
        : "r"(a0), "r"(a1), "r"(a2), "r"(a3), "r"(b0), "r"(b1));
}
__device__ __forceinline__ void ldsm_x4(unsigned& r0, unsigned& r1,
                                        unsigned& r2, unsigned& r3, unsigned a) {
    asm volatile("ldmatrix.sync.aligned.m8n8.x4.shared.b16 {%0,%1,%2,%3}, [%4];"
                 : "=r"(r0), "=r"(r1), "=r"(r2), "=r"(r3) : "r"(a));
}
__device__ __forceinline__ void cp16(void* d, const void* s) {
    unsigned a = (unsigned)__cvta_generic_to_shared(d);
    asm volatile("cp.async.cg.shared.global [%0], [%1], 16;" :: "r"(a), "l"(s));
}
__device__ __forceinline__ void cp_commit() {
    asm volatile("cp.async.commit_group;");
}
template<int N> __device__ __forceinline__ void cp_wait() {
    asm volatile("cp.async.wait_group %0;" :: "n"(N));
}

#define LN2   0.69314718056f
#define RLN2  1.44269504089f

__device__ __forceinline__ float softplus_fast(float x) {
    float e = f_ex2(-fabsf(x) * RLN2);
    return fmaxf(x, 0.f) + f_lg2(1.f + e) * LN2;
}

// HardKuma epilogue, fused shift-2 Stirling Beta (saves ~12 FMA vs shift-4)
__device__ __forceinline__ float kuma_out(float ar, float br) {
    const float K_T0 = -3.58496250072f;   // log2(1/12)
    const float K_T1 = -0.12553088208f;   // log2(11/12)
    float a  = fminf(fmaxf(softplus_fast(ar), 0.01f), 100.f);
    float bb = fminf(fmaxf(softplus_fast(br), 0.01f), 100.f);
    float u0 = f_ex2(a * K_T0);
    float u1 = f_ex2(a * K_T1);
    float E0 = f_ex2(bb * f_lg2(1.f - u0));  // 1 - p0
    float p1 = f_ex2(bb * f_lg2(1.f - u1));
    float pc = E0 - p1;

    // lnB = S2(y1)+S2(y2)-S2(y3) + c + ln(ps/(pg*pb)), shift-by-2:
    // y=x+2, products x(x+1); linear terms sum to -2.
    float g  = 1.f + f_rcp(a);
    float s  = g + bb;
    float y1 = g + 2.f, y2 = bb + 2.f, y3 = s + 2.f;
    float L1 = f_lg2(y1), L2 = f_lg2(y2), L3 = f_lg2(y3);
    float pg = g  * (g  + 1.f);
    float pb = bb * (bb + 1.f);
    float ps = s  * (s  + 1.f);
    float pgb = pg * pb;
    float d3  = y1 * y2 * y3;
    float inv = f_rcp(d3 * pgb);
    float n   = fmaf(y1, y3, fmaf(y2, y3, -y1 * y2));  // y2y3 + y1y3 - y1y2
    float c   = 0.08333333333f * (n * pgb) * inv;
    float R   = ps * d3 * inv;
    // const: -2 + 0.5*ln(2pi) = -1.08106146679
    float lm2 = (y1 - 0.5f) * L1 + (y2 - 0.5f) * L2 - (y3 - 0.5f) * L3
              + (c - 1.08106146679f) * RLN2;
    float mean = bb * R * f_ex2(lm2);
    mean = fminf(fmaxf(fmaf(1.2f, mean, -0.1f), 0.f), 1.f);

    float zo = (1.f - E0 > p1) ? 0.f : 1.f;
    return (pc < 0.5f) ? zo : mean;
}

// ---------------------------------------------------------------------------
// Weight transpose + fp16 convert. grid = 512 x 256 threads.
// ---------------------------------------------------------------------------
__global__ void prep_w_kernel(
    const float* __restrict__ Wa1, const float* __restrict__ Wb1,
    const float* __restrict__ Wa2, const float* __restrict__ Wb2,
    __half* __restrict__ T1a, __half* __restrict__ T1b,
    __half* __restrict__ T2a, __half* __restrict__ T2b)
{
    __shared__ float t[32][33];
    int idx = blockIdx.x;
    int z  = idx >> 7;
    int rem = idx & 127;
    int gy = rem >> 4, gx = rem & 15;
    int K = (z < 2) ? DIN : DOUT;
    if (gx * 32 >= K) return;
    const float* S = (z == 0) ? Wa1 : (z == 1) ? Wb1 : (z == 2) ? Wa2 : Wb2;
    __half*      D = (z == 0) ? T1a : (z == 1) ? T1b : (z == 2) ? T2a : T2b;

    int kb = gx * 32, nb = gy * 32;
    int tid = threadIdx.x;
    int x = tid & 31, y = tid >> 5;
#pragma unroll
    for (int i = 0; i < 32; i += 8)
        t[y + i][x] = S[(long)(kb + y + i) * DOUT + nb + x];
    __syncthreads();
#pragma unroll
    for (int i = 0; i < 32; i += 8)
        D[(long)(nb + y + i) * K + kb + x] = __float2half(t[x][y + i]);
}

// ---------------------------------------------------------------------------
// fp16 MLP GEMM, cp.async 4-stage (weights), ldmatrix + mma.m16n8k16.
// FP32IN=1: X fp32 (Xq rows <8192, Xk rows >=8192), converted in-register.
// FP32IN=0: X fp16 via cp.async.
// grid = (4, 128). Block tile 128x128, warps 2(m)x4(n), warp tile 64x32.
// ---------------------------------------------------------------------------
#define MLPH_TILE_U32 2560
#define MLPH_SMEM_BYTES (4 * 2 * MLPH_TILE_U32 * 4)   // 81920

template<int FP32IN>
__global__ void __launch_bounds__(256, 2) mlp_f16_kernel(
    const void* __restrict__ Xq1v, const void* __restrict__ Xk1v,
    const __half* __restrict__ Wt1,
    const float* __restrict__ bias1, __half* __restrict__ C1,
    const void* __restrict__ Xq2v, const void* __restrict__ Xk2v,
    const __half* __restrict__ Wt2,
    const float* __restrict__ bias2, __half* __restrict__ C2,
    int K)
{
    extern __shared__ unsigned sm[];
    unsigned* ASb = sm;
    unsigned* BSb = sm + 4 * MLPH_TILE_U32;

    int set = blockIdx.x >> 1;
    int bn  = blockIdx.x & 1;
    long rbase = (long)blockIdx.y * 128;

    const void*   Xqv  = set ? Xq2v : Xq1v;
    const void*   Xkv  = set ? Xk2v : Xk1v;
    const __half* Wb   = (set ? Wt2 : Wt1) + (long)(bn * 128) * K;
    const float*  bias = set ? bias2 : bias1;
    __half*       C    = set ? C2  : C1;

    // row-base source select (k tensor for rows >= 8192)
    const void* Xv;
    long xoff;
    if (Xkv != nullptr && rbase >= 8192) { Xv = Xkv; xoff = rbase - 8192; }
    else                                 { Xv = Xqv; xoff = rbase; }
    const float*  Xf = (const float*)Xv + xoff * K;
    const __half* Xh = (const __half*)Xv + xoff * K;

    int tid = threadIdx.x;
    int wid = tid >> 5, lane = tid & 31;
    int wm  = wid >> 2, wn = wid & 3;
    int g   = lane >> 2, t4 = lane & 3;

    int r0 = tid >> 2,          c0 = tid & 3;
    int r1 = (tid + 256) >> 2,  c1 = (tid + 256) & 3;

    int l7 = lane & 7, l8 = (lane >> 3) & 1, l16 = (lane >> 4) & 1;
    unsigned aoff = (unsigned)((wm * 64 + l7 + l8 * 8) * 80 + l16 * 16);
    unsigned boff = (unsigned)((wn * 32 + l7 + l16 * 8) * 80 + l8 * 16);
    unsigned aBase = (unsigned)__cvta_generic_to_shared(ASb);
    unsigned bBase = (unsigned)__cvta_generic_to_shared(BSb);

    float acc[4][4][4];
#pragma unroll
    for (int mt = 0; mt < 4; mt++)
#pragma unroll
        for (int nt = 0; nt < 4; nt++)
#pragma unroll
            for (int c = 0; c < 4; c++) acc[mt][nt][c] = 0.f;

    const int ITERS = K >> 5;

    float4 xa0, xb0, xa1, xb1;   // FP32IN staging

#define W_ISSUE(ki) do {                                                      \
        int st_ = (ki) & 3; int k0_ = (ki) << 5;                              \
        unsigned* B_ = BSb + st_ * MLPH_TILE_U32;                             \
        cp16(B_ + r0 * 20 + c0 * 4, Wb + (long)r0 * K + k0_ + c0 * 8);        \
        cp16(B_ + r1 * 20 + c1 * 4, Wb + (long)r1 * K + k0_ + c1 * 8);        \
    } while (0)

#define X_ISSUE_H(ki) do {                                                    \
        int st_ = (ki) & 3; int k0_ = (ki) << 5;                              \
        unsigned* A_ = ASb + st_ * MLPH_TILE_U32;                             \
        cp16(A_ + r0 * 20 + c0 * 4, Xh + (long)r0 * K + k0_ + c0 * 8);        \
        cp16(A_ + r1 * 20 + c1 * 4, Xh + (long)r1 * K + k0_ + c1 * 8);        \
    } while (0)

#define X_LOAD_F(ki) do {                                                     \
        int k0_ = (ki) << 5;                                                  \
        const float* p0_ = Xf + (long)r0 * K + k0_ + c0 * 8;                  \
        const float* p1_ = Xf + (long)r1 * K + k0_ + c1 * 8;                  \
        xa0 = *(const float4*)p0_;  xb0 = *(const float4*)(p0_ + 4);          \
        xa1 = *(const float4*)p1_;  xb1 = *(const float4*)(p1_ + 4);          \
    } while (0)

#define X_STORE_F(ki) do {                                                    \
        int st_ = (ki) & 3;                                                   \
        unsigned* A_ = ASb + st_ * MLPH_TILE_U32;                             \
        __half2 h_[4];                                                        \
        h_[0] = __floats2half2_rn(xa0.x, xa0.y);                              \
        h_[1] = __floats2half2_rn(xa0.z, xa0.w);                              \
        h_[2] = __floats2half2_rn(xb0.x, xb0.y);                              \
        h_[3] = __floats2half2_rn(xb0.z, xb0.w);                              \
        *(uint4*)(A_ + r0 * 20 + c0 * 4) = *(uint4*)h_;                       \
        h_[0] = __floats2half2_rn(xa1.x, xa1.y);                              \
        h_[1] = __floats2half2_rn(xa1.z, xa1.w);                              \
        h_[2] = __floats2half2_rn(xb1.x, xb1.y);                              \
        h_[3] = __floats2half2_rn(xb1.z, xb1.w);                              \
        *(uint4*)(A_ + r1 * 20 + c1 * 4) = *(uint4*)h_;                       \
    } while (0)

    if (FP32IN) {
        X_LOAD_F(0); X_STORE_F(0);
        X_LOAD_F(1); X_STORE_F(1);
        W_ISSUE(0); cp_commit();
        W_ISSUE(1); cp_commit();
        W_ISSUE(2); cp_commit();
    } else {
        X_ISSUE_H(0); W_ISSUE(0); cp_commit();
        X_ISSUE_H(1); W_ISSUE(1); cp_commit();
        X_ISSUE_H(2); W_ISSUE(2); cp_commit();
    }

    for (int it = 0; it < ITERS; it++) {
        cp_wait<2>();
        __syncthreads();
        if (it + 3 < ITERS) W_ISSUE(it + 3);
        if (!FP32IN) { if (it + 3 < ITERS) X_ISSUE_H(it + 3); }
        cp_commit();
        if (FP32IN) { if (it + 2 < ITERS) X_LOAD_F(it + 2); }

        int st = it & 3;
        unsigned aS = aBase + st * (MLPH_TILE_U32 * 4);
        unsigned bS = bBase + st * (MLPH_TILE_U32 * 4);

#pragma unroll
        for (int k16 = 0; k16 < 2; k16++) {
            unsigned kbyt = k16 * 32;
            unsigned af[4][4], bf[2][4];
#pragma unroll
            for (int mt = 0; mt < 4; mt++)
                ldsm_x4(af[mt][0], af[mt][1], af[mt][2], af[mt][3],
                        aS + aoff + mt * 1280 + kbyt);
#pragma unroll
            for (int ntp = 0; ntp < 2; ntp++)
                ldsm_x4(bf[ntp][0], bf[ntp][1], bf[ntp][2], bf[ntp][3],
                        bS + boff + ntp * 1280 + kbyt);
#pragma unroll
            for (int nt = 0; nt < 4; nt++) {
                unsigned b0 = bf[nt >> 1][(nt & 1) * 2];
                unsigned b1 = bf[nt >> 1][(nt & 1) * 2 + 1];
#pragma unroll
                for (int mt = 0; mt < 4; mt++)
                    mma_f16(acc[mt][nt][0], acc[mt][nt][1],
                            acc[mt][nt][2], acc[mt][nt][3],
                            af[mt][0], af[mt][1], af[mt][2], af[mt][3],
                            b0, b1);
            }
        }

        if (FP32IN) { if (it + 2 < ITERS) X_STORE_F(it + 2); }
    }

    // epilogue: bias + relu, fp16 out
#pragma unroll
    for (int mt = 0; mt < 4; mt++) {
#pragma unroll
        for (int rr = 0; rr < 2; rr++) {
            long row = rbase + wm * 64 + mt * 16 + g + rr * 8;
#pragma unroll
            for (int nt = 0; nt < 4; nt++) {
                int col = bn * 128 + wn * 32 + nt * 8 + t4 * 2;
                float ox = fmaxf(acc[mt][nt][rr*2+0] + bias[col    ], 0.f);
                float oy = fmaxf(acc[mt][nt][rr*2+1] + bias[col + 1], 0.f);
                *(__half2*)(C + row * DOUT + col) = __floats2half2_rn(ox, oy);
            }
        }
    }
}

// ---------------------------------------------------------------------------
// fp16 fused score GEMM (a & b) + HardKuma epilogue — R13 shape + uniform-rd
// fast path for off-band tiles (~90% of tiles skip per-element clamp/lookup).
// ---------------------------------------------------------------------------
#define Q_TILE_U32 2560
#define K_TILE_U32 1280
#define ATTN_SMEM_BYTES (3 * (2 * Q_TILE_U32 + 2 * K_TILE_U32) * 4)

__global__ void __launch_bounds__(256, 2) kuma_attn_f16_kernel(
    const unsigned short* __restrict__ Au, const unsigned short* __restrict__ Bu,
    const float* __restrict__ dist_emb, float* __restrict__ out)
{
    extern __shared__ unsigned sm[];
    unsigned* QAb = sm;
    unsigned* QBb = sm + 3 * Q_TILE_U32;
    unsigned* KAb = sm + 6 * Q_TILE_U32;
    unsigned* KBb = sm + 6 * Q_TILE_U32 + 3 * K_TILE_U32;
    __shared__ float sdist[23];

    const __half* Ah = (const __half*)Au;
    const __half* Bh = (const __half*)Bu;

    int b  = blockIdx.z;
    int bt = blockIdx.y * 128;
    int bs = blockIdx.x * 64;
    int tid = threadIdx.x;
    if (tid < 23) sdist[tid] = dist_emb[tid];

    int wid = tid >> 5, lane = tid & 31;
    int wm  = wid >> 1, wn = wid & 1;
    int g   = lane >> 2, t4 = lane & 3;

    const __half* qa = Ah + ((long)b * T_SEQ + bt) * DOUT;
    const __half* ka = Ah + ((long)(8192 + b * T_SEQ) + bs) * DOUT;
    const __half* qb = Bh + ((long)b * T_SEQ + bt) * DOUT;
    const __half* kb = Bh + ((long)(8192 + b * T_SEQ) + bs) * DOUT;

    int rQ0 = tid >> 2,         cQ0 = (tid & 3);
    int rQ1 = (tid + 256) >> 2, cQ1 = ((tid + 256) & 3);
    int rK = tid >> 2,          cK  = (tid & 3);

    int l7 = lane & 7, l8 = (lane >> 3) & 1, l16 = (lane >> 4) & 1;
    unsigned aoff = (unsigned)((wm * 32 + l7 + l8 * 8) * 80 + l16 * 16);
    unsigned boff = (unsigned)((wn * 32 + l7 + l16 * 8) * 80 + l8 * 16);
    unsigned qaB = (unsigned)__cvta_generic_to_shared(QAb);
    unsigned qbB = (unsigned)__cvta_generic_to_shared(QBb);
    unsigned kaB = (unsigned)__cvta_generic_to_shared(KAb);
    unsigned kbB = (unsigned)__cvta_generic_to_shared(KBb);

    // tile band classification (block-uniform)
    int minRel = bs - (bt + 127);      // min over tile of (s - t)
    int maxRel = (bs + 63) - bt;       // max over tile
    bool uniHi = (minRel >= 11);
    bool uniLo = (maxRel <= -11);
    bool uni   = uniHi || uniLo;

    float accA[2][4][4], accB[2][4][4];
#pragma unroll
    for (int mt = 0; mt < 2; mt++)
#pragma unroll
        for (int nt = 0; nt < 4; nt++)
#pragma unroll
            for (int c = 0; c < 4; c++) { accA[mt][nt][c] = 0.f; accB[mt][nt][c] = 0.f; }

    const int ITERS = DOUT >> 5;   // 8

#define ATTN_ISSUE(ki) do {                                                   \
        int st_ = (ki) % 3; int k0_ = (ki) << 5;                              \
        unsigned* QA_ = QAb + st_ * Q_TILE_U32;                               \
        unsigned* QB_ = QBb + st_ * Q_TILE_U32;                               \
        unsigned* KA_ = KAb + st_ * K_TILE_U32;                               \
        unsigned* KB_ = KBb + st_ * K_TILE_U32;                               \
        cp16(QA_ + rQ0 * 20 + cQ0 * 4, qa + (long)rQ0 * DOUT + k0_ + cQ0 * 8);\
        cp16(QA_ + rQ1 * 20 + cQ1 * 4, qa + (long)rQ1 * DOUT + k0_ + cQ1 * 8);\
        cp16(QB_ + rQ0 * 20 + cQ0 * 4, qb + (long)rQ0 * DOUT + k0_ + cQ0 * 8);\
        cp16(QB_ + rQ1 * 20 + cQ1 * 4, qb + (long)rQ1 * DOUT + k0_ + cQ1 * 8);\
        cp16(KA_ + rK * 20 + cK * 4, ka + (long)rK * DOUT + k0_ + cK * 8);    \
        cp16(KB_ + rK * 20 + cK * 4, kb + (long)rK * DOUT + k0_ + cK * 8);    \
    } while (0)

    ATTN_ISSUE(0); cp_commit();
    ATTN_ISSUE(1); cp_commit();

    for (int it = 0; it < ITERS; it++) {
        cp_wait<1>();
        __syncthreads();
        if (it + 2 < ITERS) ATTN_ISSUE(it + 2);
        cp_commit();

        int st = it % 3;
        unsigned qaS = qaB + st * (Q_TILE_U32 * 4);
        unsigned qbS = qbB + st * (Q_TILE_U32 * 4);
        unsigned kaS = kaB + st * (K_TILE_U32 * 4);
        unsigned kbS = kbB + st * (K_TILE_U32 * 4);

#pragma unroll
        for (int k16 = 0; k16 < 2; k16++) {
            unsigned kbyt = k16 * 32;
            unsigned qaf[2][4], qbf[2][4], kaf[2][4], kbf[2][4];
#pragma unroll
            for (int mt = 0; mt < 2; mt++) {
                ldsm_x4(qaf[mt][0], qaf[mt][1], qaf[mt][2], qaf[mt][3],
                        qaS + aoff + mt * 1280 + kbyt);
                ldsm_x4(qbf[mt][0], qbf[mt][1], qbf[mt][2], qbf[mt][3],
                        qbS + aoff + mt * 1280 + kbyt);
            }
#pragma unroll
            for (int ntp = 0; ntp < 2; ntp++) {
                ldsm_x4(kaf[ntp][0], kaf[ntp][1], kaf[ntp][2], kaf[ntp][3],
                        kaS + boff + ntp * 1280 + kbyt);
                ldsm_x4(kbf[ntp][0], kbf[ntp][1], kbf[ntp][2], kbf[ntp][3],
                        kbS + boff + ntp * 1280 + kbyt);
            }
#pragma unroll
            for (int nt = 0; nt < 4; nt++) {
                unsigned bA0 = kaf[nt >> 1][(nt & 1) * 2];
                unsigned bA1 = kaf[nt >> 1][(nt & 1) * 2 + 1];
                unsigned bB0 = kbf[nt >> 1][(nt & 1) * 2];
                unsigned bB1 = kbf[nt >> 1][(nt & 1) * 2 + 1];
#pragma unroll
                for (int mt = 0; mt < 2; mt++) {
                    mma_f16(accA[mt][nt][0], accA[mt][nt][1],
                            accA[mt][nt][2], accA[mt][nt][3],
                            qaf[mt][0], qaf[mt][1], qaf[mt][2], qaf[mt][3],
                            bA0, bA1);
                    mma_f16(accB[mt][nt][0], accB[mt][nt][1],
                            accB[mt][nt][2], accB[mt][nt][3],
                            qbf[mt][0], qbf[mt][1], qbf[mt][2], qbf[mt][3],
                            bB0, bB1);
                }
            }
        }
    }

    // HardKuma epilogue + store
    if (uni) {
        float rdU = sdist[uniHi ? 22 : 0];
#pragma unroll
        for (int mt = 0; mt < 2; mt++) {
#pragma unroll
            for (int rr = 0; rr < 2; rr++) {
                int trow = bt + wm * 32 + mt * 16 + g + rr * 8;
#pragma unroll
                for (int nt = 0; nt < 4; nt++) {
                    int scol = bs + wn * 32 + nt * 8 + t4 * 2;
                    float2 o;
                    o.x = kuma_out(accA[mt][nt][rr*2+0] + rdU, accB[mt][nt][rr*2+0] + rdU);
                    o.y = kuma_out(accA[mt][nt][rr*2+1] + rdU, accB[mt][nt][rr*2+1] + rdU);
                    *(float2*)(out + ((long)b * T_SEQ + trow) * T_SEQ + scol) = o;
                }
            }
        }
    } else {
#pragma unroll
        for (int mt = 0; mt < 2; mt++) {
#pragma unroll
            for (int rr = 0; rr < 2; rr++) {
                int trow = bt + wm * 32 + mt * 16 + g + rr * 8;
#pragma unroll
                for (int nt = 0; nt < 4; nt++) {
                    int scol = bs + wn * 32 + nt * 8 + t4 * 2;
                    int rel0 = max(-11, min(11, scol     - trow)) + 11;
                    int rel1 = max(-11, min(11, scol + 1 - trow)) + 11;
                    float rd0 = sdist[rel0], rd1 = sdist[rel1];
                    float2 o;
                    o.x = kuma_out(accA[mt][nt][rr*2+0] + rd0, accB[mt][nt][rr*2+0] + rd0);
                    o.y = kuma_out(accA[mt][nt][rr*2+1] + rd1, accB[mt][nt][rr*2+1] + rd1);
                    *(float2*)(out + ((long)b * T_SEQ + trow) * T_SEQ + scol) = o;
                }
            }
        }
    }
}

// ---------------------------------------------------------------------------
extern "C" void kernel_launch(void* const* d_in, const int* in_sizes, int n_in,
                              void* d_out, int out_size)
{
    const float* q    = (const float*)d_in[0];
    const float* k    = (const float*)d_in[1];
    const float* Wa1  = (const float*)d_in[2];
    const float* ba1  = (const float*)d_in[3];
    const float* Wa2  = (const float*)d_in[4];
    const float* ba2  = (const float*)d_in[5];
    const float* Wb1  = (const float*)d_in[6];
    const float* bb1  = (const float*)d_in[7];
    const float* Wb2  = (const float*)d_in[8];
    const float* bb2  = (const float*)d_in[9];
    const float* dist = (const float*)d_in[10];
    float* out = (float*)d_out;

    unsigned short *h1, *h2, *Ah, *Bh, *t1a, *t1b, *t2a, *t2b;
    cudaGetSymbolAddress((void**)&h1,  g_h1);
    cudaGetSymbolAddress((void**)&h2,  g_h2);
    cudaGetSymbolAddress((void**)&Ah,  g_A);
    cudaGetSymbolAddress((void**)&Bh,  g_B);
    cudaGetSymbolAddress((void**)&t1a, g_Wt1a);
    cudaGetSymbolAddress((void**)&t1b, g_Wt1b);
    cudaGetSymbolAddress((void**)&t2a, g_Wt2a);
    cudaGetSymbolAddress((void**)&t2b, g_Wt2b);

    cudaFuncSetAttribute(mlp_f16_kernel<0>,
        cudaFuncAttributeMaxDynamicSharedMemorySize, MLPH_SMEM_BYTES);
    cudaFuncSetAttribute(mlp_f16_kernel<1>,
        cudaFuncAttributeMaxDynamicSharedMemorySize, MLPH_SMEM_BYTES);
    cudaFuncSetAttribute(kuma_attn_f16_kernel,
        cudaFuncAttributeMaxDynamicSharedMemorySize, ATTN_SMEM_BYTES);

    prep_w_kernel<<<512, 256>>>(Wa1, Wb1, Wa2, Wb2,
        (__half*)t1a, (__half*)t1b, (__half*)t2a, (__half*)t2b);

    dim3 g1(4, 128);
    // layer 1: q rows (<8192) and k rows (>=8192) in one launch, fp32 in
    mlp_f16_kernel<1><<<g1, 256, MLPH_SMEM_BYTES>>>(
        (const void*)q, (const void*)k, (const __half*)t1a, ba1, (__half*)h1,
        (const void*)q, (const void*)k, (const __half*)t1b, bb1, (__half*)h2, DIN);
    // layer 2: fp16 in
    mlp_f16_kernel<0><<<g1, 256, MLPH_SMEM_BYTES>>>(
        (const void*)h1, nullptr, (const __half*)t2a, ba2, (__half*)Ah,
        (const void*)h2, nullptr, (const __half*)t2b, bb2, (__half*)Bh, DOUT);

    dim3 g2(T_SEQ / 64, T_SEQ / 128, BATCH);
    kuma_attn_f16_kernel<<<g2, 256, ATTN_SMEM_BYTES>>>(Ah, Bh, dist, out);
}